// round 12
// baseline (speedup 1.0000x reference)
#include <cuda_runtime.h>
#include <math.h>

#define N_NODES 50000
#define TPB_N   128
#define NPB     114          // nodes per block
#define GRID_N  444          // 148 * 3, NPB*GRID_N = 50616 >= N_NODES
#define TPB_E   128
#define GRID_E  592          // 148 SMs * 4 CTAs -> exactly one wave

// Scratch (allocation-free __device__ globals). Zero-initialized at load;
// K2's last block resets counters each launch -> deterministic across replays.
__device__ double   g_acc;
__device__ unsigned g_done;
__device__ unsigned g_ready;                // setup rows published (0..16)
__device__ float    g_Wt[16 * 64];          // 16 weight rows
__device__ float4   g_vtab[8 * N_NODES];    // [rel][node]: (v0, v1, vb, 0)

typedef unsigned long long u64;
#define FMA2(d, a, b) \
    asm("fma.rn.f32x2 %0, %1, %2, %0;" : "+l"(d) : "l"(a), "l"(b))

__device__ __forceinline__ double block_reduce(double v, int nthreads) {
    __shared__ double sh[8];
    int lane = threadIdx.x & 31, wid = threadIdx.x >> 5;
    #pragma unroll
    for (int off = 16; off; off >>= 1) v += __shfl_down_sync(0xffffffffu, v, off);
    if (lane == 0) sh[wid] = v;
    __syncthreads();
    int nw = nthreads >> 5;
    v = (threadIdx.x < nw) ? sh[threadIdx.x] : 0.0;
    if (wid == 0) {
        #pragma unroll
        for (int off = 4; off; off >>= 1) v += __shfl_down_sync(0xffffffffu, v, off);
    }
    return v;
}

// ---------------------------------------------------------------------------
// K1: node pass (unchanged from R11); blocks 0..15 each compute ONE row of
// the 16x64 weight table, publish via g_ready. All 444 blocks co-resident
// (3 CTAs/SM at ~32KB smem) -> spin cannot deadlock.
// ---------------------------------------------------------------------------
#define TSTRIDE 68           // floats per padded tile row (16B-aligned rows)

__global__ void __launch_bounds__(TPB_N)
k_node(const float2* __restrict__ feats,
       const float* __restrict__ W_in, const float* __restrict__ b_in,
       const float* __restrict__ w_comp, const float* __restrict__ bases,
       const float* __restrict__ loop_w, const float* __restrict__ h_bias,
       const float* __restrict__ fcW)
{
    __shared__ float  tile[NPB * TSTRIDE];   // 31 KB
    __shared__ float4 ws[16 * 16];           // 16 rows x 64 floats
    __shared__ float  wc[32];
    __shared__ float  hv[64];
    __shared__ float  part[2][64];
    int tid = threadIdx.x;

    if (tid < 32) wc[tid] = w_comp[tid];

    if (blockIdx.x < 16) {
        int row = blockIdx.x;
        if (row == 15) {
            if (tid < 64) g_Wt[15 * 64 + tid] = h_bias[tid];
        } else {
            int c; const float* M;
            if (row < 12) { c = row >> 2; M = bases + (row & 3) * 4096; }
            else          { c = row - 12; M = loop_w; }
            if (tid < 64) hv[tid] = (c < 2) ? W_in[c * 64 + tid] : b_in[tid];
            __syncthreads();
            int o = tid & 63, q = tid >> 6;
            float s = 0.f;
            int i0 = q * 32;
            #pragma unroll 16
            for (int i = 0; i < 32; i++)
                s += hv[i0 + i] * __ldg(&M[(i0 + i) * 64 + o]);
            part[q][o] = s;
            __syncthreads();
            if (tid < 64)
                g_Wt[row * 64 + tid] = part[0][tid] + part[1][tid];
        }
        __syncthreads();
        if (tid == 0) {
            __threadfence();
            atomicAdd(&g_ready, 1u);
        }
    }

    int nbase = blockIdx.x * NPB;
    int nblk  = min(NPB, N_NODES - nbase);
    if (nblk > 0) {
        const float4* src4 = (const float4*)(fcW + (size_t)nbase * 64);
        int total4 = nblk * 16;
        for (int idx = tid; idx < total4; idx += TPB_N) {
            float4 f = src4[idx];
            int node = idx >> 4, j4 = idx & 15;
            ((float4*)(tile + node * TSTRIDE))[j4] = f;
        }
    }

    if (tid == 0) {
        while (atomicAdd(&g_ready, 0u) < 16u) { }
        __threadfence();
    }
    __syncthreads();
    for (int i = tid; i < 16 * 16; i += TPB_N)
        ws[i] = ((const float4*)g_Wt)[i];
    __syncthreads();

    double contrib = 0.0;
    if (nblk > 0 && tid < nblk) {
        int n = nbase + tid;
        const ulonglong2* F2 = (const ulonglong2*)(tile + tid * TSTRIDE);
        const ulonglong2* W2 = (const ulonglong2*)ws;
        u64 acc2[16];
        #pragma unroll
        for (int k = 0; k < 16; k++) acc2[k] = 0ull;
        #pragma unroll 4
        for (int j = 0; j < 16; j++) {
            ulonglong2 f = F2[j];
            #pragma unroll
            for (int k = 0; k < 16; k++) {
                ulonglong2 w = W2[k * 16 + j];
                FMA2(acc2[k], f.x, w.x);
                FMA2(acc2[k], f.y, w.y);
            }
        }
        float acc[16];
        #pragma unroll
        for (int k = 0; k < 16; k++) {
            union { u64 u; float2 f2; } cv; cv.u = acc2[k];
            acc[k] = cv.f2.x + cv.f2.y;
        }
        #pragma unroll
        for (int r = 0; r < 8; r++) {
            float4 v;
            v.x = wc[r*4]*acc[0] + wc[r*4+1]*acc[1] + wc[r*4+2]*acc[2]  + wc[r*4+3]*acc[3];
            v.y = wc[r*4]*acc[4] + wc[r*4+1]*acc[5] + wc[r*4+2]*acc[6]  + wc[r*4+3]*acc[7];
            v.z = wc[r*4]*acc[8] + wc[r*4+1]*acc[9] + wc[r*4+2]*acc[10] + wc[r*4+3]*acc[11];
            v.w = 0.f;
            g_vtab[r * N_NODES + n] = v;     // lane-coalesced per r
        }
        float2 f = feats[n];
        contrib = (double)(f.x * acc[12] + f.y * acc[13] + acc[14] + acc[15]);
    }
    double bs = block_reduce(contrib, TPB_N);
    if (tid == 0) atomicAdd(&g_acc, bs);
}

// ---------------------------------------------------------------------------
// K2: edge pass + finalize. 2-deep software pipeline: group i+1's gathers are
// issued BEFORE group i's values are consumed; indices prefetched 2 ahead.
// The 260-cyc gather latency overlaps a full iteration of issue+FMA.
// One exact wave: 592 blocks @ 4 CTAs/SM (<=128 regs, no spills).
// ---------------------------------------------------------------------------
__global__ void __launch_bounds__(TPB_E, 4)
k_edge(const float2* __restrict__ feats,
       const int* __restrict__ src, const int* __restrict__ dst,
       const int* __restrict__ et, const float* __restrict__ fc_b,
       int E, float* __restrict__ out)
{
    double contrib = 0.0;
    int nvec = E >> 2;
    const int4* s4p = (const int4*)src;
    const int4* d4p = (const int4*)dst;
    const int4* r4p = (const int4*)et;
    const int stride = GRID_E * TPB_E;

    int i = blockIdx.x * TPB_E + threadIdx.x;
    if (i < nvec) {
        // Stage 0: indices + gathers for group 0
        int4 s0 = s4p[i], d0 = d4p[i], r0 = r4p[i];
        float2 fa0 = feats[s0.x], fb0 = feats[s0.y], fc0 = feats[s0.z], fd0 = feats[s0.w];
        float4 va0 = g_vtab[r0.x * N_NODES + d0.x];
        float4 vb0 = g_vtab[r0.y * N_NODES + d0.y];
        float4 vc0 = g_vtab[r0.z * N_NODES + d0.z];
        float4 vd0 = g_vtab[r0.w * N_NODES + d0.w];
        // Indices for group 1
        int j = i + stride;
        bool have1 = j < nvec;
        int4 s1, d1, r1;
        if (have1) { s1 = s4p[j]; d1 = d4p[j]; r1 = r4p[j]; }

        while (true) {
            // Issue group-1 gathers (independent of group-0 consume)
            float2 fa1, fb1, fc1, fd1;
            float4 va1, vb1, vc1, vd1;
            if (have1) {
                fa1 = feats[s1.x]; fb1 = feats[s1.y];
                fc1 = feats[s1.z]; fd1 = feats[s1.w];
                va1 = g_vtab[r1.x * N_NODES + d1.x];
                vb1 = g_vtab[r1.y * N_NODES + d1.y];
                vc1 = g_vtab[r1.z * N_NODES + d1.z];
                vd1 = g_vtab[r1.w * N_NODES + d1.w];
            }
            // Prefetch group-2 indices
            int k = j + stride;
            bool have2 = have1 && (k < nvec);
            int4 s2, d2, r2;
            if (have2) { s2 = s4p[k]; d2 = d4p[k]; r2 = r4p[k]; }

            // Consume group 0 (its gathers were issued one iteration ago)
            float esum = fmaf(fa0.x, va0.x, fmaf(fa0.y, va0.y, va0.z))
                       + fmaf(fb0.x, vb0.x, fmaf(fb0.y, vb0.y, vb0.z))
                       + fmaf(fc0.x, vc0.x, fmaf(fc0.y, vc0.y, vc0.z))
                       + fmaf(fd0.x, vd0.x, fmaf(fd0.y, vd0.y, vd0.z));
            contrib += (double)esum;
            if (!have1) break;

            // Rotate pipeline
            fa0 = fa1; fb0 = fb1; fc0 = fc1; fd0 = fd1;
            va0 = va1; vb0 = vb1; vc0 = vc1; vd0 = vd1;
            s1 = s2; d1 = d2; r1 = r2;
            j = k; have1 = have2;
        }
    }
    // tail edges (if E not multiple of 4)
    for (int e = (nvec << 2) + blockIdx.x * TPB_E + threadIdx.x; e < E; e += stride) {
        float2 f = feats[src[e]];
        float4 v = g_vtab[et[e] * N_NODES + dst[e]];
        contrib += (double)fmaf(f.x, v.x, fmaf(f.y, v.y, v.z));
    }

    double bs = block_reduce(contrib, TPB_E);
    if (threadIdx.x == 0) {
        atomicAdd(&g_acc, bs);
        __threadfence();
        unsigned d = atomicAdd(&g_done, 1u);
        if (d == GRID_E - 1) {
            double logit = atomicAdd(&g_acc, 0.0) + (double)fc_b[0];
            out[0] = (float)(1.0 / (1.0 + exp(-logit)));
            g_acc = 0.0;       // reset for next graph replay
            g_done = 0u;
            g_ready = 0u;
        }
    }
}

extern "C" void kernel_launch(void* const* d_in, const int* in_sizes, int n_in,
                              void* d_out, int out_size) {
    const float* features = (const float*)d_in[0];
    const int*   src      = (const int*)d_in[1];
    const int*   dst      = (const int*)d_in[2];
    const int*   etype    = (const int*)d_in[3];
    const float* W_in     = (const float*)d_in[4];
    const float* b_in     = (const float*)d_in[5];
    const float* w_comp   = (const float*)d_in[6];
    const float* bases    = (const float*)d_in[7];
    const float* loop_w   = (const float*)d_in[8];
    const float* h_bias   = (const float*)d_in[9];
    const float* fc_W     = (const float*)d_in[10];
    const float* fc_b     = (const float*)d_in[11];
    int E = in_sizes[1];

    k_node<<<GRID_N, TPB_N>>>((const float2*)features,
                              W_in, b_in, w_comp, bases,
                              loop_w, h_bias, fc_W);
    k_edge<<<GRID_E, TPB_E>>>((const float2*)features, src, dst, etype,
                              fc_b, E, (float*)d_out);
}

// round 13
// speedup vs baseline: 1.0268x; 1.0268x over previous
#include <cuda_runtime.h>
#include <math.h>

#define N_NODES 50000
#define TPB_N   128
#define NPB     114          // nodes per block
#define GRID_N  444          // 148 * 3, NPB*GRID_N = 50616 >= N_NODES
#define TPB_E   128
#define GRID_E  888          // 148 SMs * 6 CTAs -> exactly one wave

// Scratch (allocation-free __device__ globals). Zero-initialized at load;
// K2's last block resets counters each launch -> deterministic across replays.
__device__ double   g_acc;
__device__ unsigned g_done;
__device__ unsigned g_ready;                // setup rows published (0..16)
__device__ float    g_Wt[16 * 64];          // 16 weight rows
__device__ float4   g_vtab[8 * N_NODES];    // [rel][node]: (v0, v1, vb, 0)

typedef unsigned long long u64;
#define FMA2(d, a, b) \
    asm("fma.rn.f32x2 %0, %1, %2, %0;" : "+l"(d) : "l"(a), "l"(b))

__device__ __forceinline__ double block_reduce(double v, int nthreads) {
    __shared__ double sh[8];
    int lane = threadIdx.x & 31, wid = threadIdx.x >> 5;
    #pragma unroll
    for (int off = 16; off; off >>= 1) v += __shfl_down_sync(0xffffffffu, v, off);
    if (lane == 0) sh[wid] = v;
    __syncthreads();
    int nw = nthreads >> 5;
    v = (threadIdx.x < nw) ? sh[threadIdx.x] : 0.0;
    if (wid == 0) {
        #pragma unroll
        for (int off = 4; off; off >>= 1) v += __shfl_down_sync(0xffffffffu, v, off);
    }
    return v;
}

// ---------------------------------------------------------------------------
// K1: node pass (unchanged from R11); blocks 0..15 each compute ONE row of
// the 16x64 weight table, publish via g_ready. All 444 blocks co-resident
// (3 CTAs/SM at ~32KB smem) -> spin cannot deadlock.
// ---------------------------------------------------------------------------
#define TSTRIDE 68           // floats per padded tile row (16B-aligned rows)

__global__ void __launch_bounds__(TPB_N)
k_node(const float2* __restrict__ feats,
       const float* __restrict__ W_in, const float* __restrict__ b_in,
       const float* __restrict__ w_comp, const float* __restrict__ bases,
       const float* __restrict__ loop_w, const float* __restrict__ h_bias,
       const float* __restrict__ fcW)
{
    __shared__ float  tile[NPB * TSTRIDE];   // 31 KB
    __shared__ float4 ws[16 * 16];           // 16 rows x 64 floats
    __shared__ float  wc[32];
    __shared__ float  hv[64];
    __shared__ float  part[2][64];
    int tid = threadIdx.x;

    if (tid < 32) wc[tid] = w_comp[tid];

    if (blockIdx.x < 16) {
        int row = blockIdx.x;
        if (row == 15) {
            if (tid < 64) g_Wt[15 * 64 + tid] = h_bias[tid];
        } else {
            int c; const float* M;
            if (row < 12) { c = row >> 2; M = bases + (row & 3) * 4096; }
            else          { c = row - 12; M = loop_w; }
            if (tid < 64) hv[tid] = (c < 2) ? W_in[c * 64 + tid] : b_in[tid];
            __syncthreads();
            int o = tid & 63, q = tid >> 6;
            float s = 0.f;
            int i0 = q * 32;
            #pragma unroll 16
            for (int i = 0; i < 32; i++)
                s += hv[i0 + i] * __ldg(&M[(i0 + i) * 64 + o]);
            part[q][o] = s;
            __syncthreads();
            if (tid < 64)
                g_Wt[row * 64 + tid] = part[0][tid] + part[1][tid];
        }
        __syncthreads();
        if (tid == 0) {
            __threadfence();
            atomicAdd(&g_ready, 1u);
        }
    }

    int nbase = blockIdx.x * NPB;
    int nblk  = min(NPB, N_NODES - nbase);
    if (nblk > 0) {
        const float4* src4 = (const float4*)(fcW + (size_t)nbase * 64);
        int total4 = nblk * 16;
        for (int idx = tid; idx < total4; idx += TPB_N) {
            float4 f = src4[idx];
            int node = idx >> 4, j4 = idx & 15;
            ((float4*)(tile + node * TSTRIDE))[j4] = f;
        }
    }

    if (tid == 0) {
        while (atomicAdd(&g_ready, 0u) < 16u) { }
        __threadfence();
    }
    __syncthreads();
    for (int i = tid; i < 16 * 16; i += TPB_N)
        ws[i] = ((const float4*)g_Wt)[i];
    __syncthreads();

    double contrib = 0.0;
    if (nblk > 0 && tid < nblk) {
        int n = nbase + tid;
        const ulonglong2* F2 = (const ulonglong2*)(tile + tid * TSTRIDE);
        const ulonglong2* W2 = (const ulonglong2*)ws;
        u64 acc2[16];
        #pragma unroll
        for (int k = 0; k < 16; k++) acc2[k] = 0ull;
        #pragma unroll 4
        for (int j = 0; j < 16; j++) {
            ulonglong2 f = F2[j];
            #pragma unroll
            for (int k = 0; k < 16; k++) {
                ulonglong2 w = W2[k * 16 + j];
                FMA2(acc2[k], f.x, w.x);
                FMA2(acc2[k], f.y, w.y);
            }
        }
        float acc[16];
        #pragma unroll
        for (int k = 0; k < 16; k++) {
            union { u64 u; float2 f2; } cv; cv.u = acc2[k];
            acc[k] = cv.f2.x + cv.f2.y;
        }
        #pragma unroll
        for (int r = 0; r < 8; r++) {
            float4 v;
            v.x = wc[r*4]*acc[0] + wc[r*4+1]*acc[1] + wc[r*4+2]*acc[2]  + wc[r*4+3]*acc[3];
            v.y = wc[r*4]*acc[4] + wc[r*4+1]*acc[5] + wc[r*4+2]*acc[6]  + wc[r*4+3]*acc[7];
            v.z = wc[r*4]*acc[8] + wc[r*4+1]*acc[9] + wc[r*4+2]*acc[10] + wc[r*4+3]*acc[11];
            v.w = 0.f;
            g_vtab[r * N_NODES + n] = v;     // lane-coalesced per r
        }
        float2 f = feats[n];
        contrib = (double)(f.x * acc[12] + f.y * acc[13] + acc[14] + acc[15]);
    }
    double bs = block_reduce(contrib, TPB_N);
    if (tid == 0) atomicAdd(&g_acc, bs);
}

// ---------------------------------------------------------------------------
// K2: edge pass + finalize. 2-deep software pipeline (group i+1's gathers
// issued before group i is consumed; indices prefetched 2 ahead) AT FULL
// WARP COUNT: 6 CTAs/SM (85-reg cap, R12 needed 78), one wave = 888 blocks,
// 24 warps/SM. Loop-local float accumulator (no dependent DADD chain).
// ---------------------------------------------------------------------------
__global__ void __launch_bounds__(TPB_E, 6)
k_edge(const float2* __restrict__ feats,
       const int* __restrict__ src, const int* __restrict__ dst,
       const int* __restrict__ et, const float* __restrict__ fc_b,
       int E, float* __restrict__ out)
{
    double contrib = 0.0;
    int nvec = E >> 2;
    const int4* s4p = (const int4*)src;
    const int4* d4p = (const int4*)dst;
    const int4* r4p = (const int4*)et;
    const int stride = GRID_E * TPB_E;

    int i = blockIdx.x * TPB_E + threadIdx.x;
    if (i < nvec) {
        float facc = 0.f;
        // Stage 0: indices + gathers for group 0
        int4 s0 = s4p[i], d0 = d4p[i], r0 = r4p[i];
        float2 fa0 = feats[s0.x], fb0 = feats[s0.y], fc0 = feats[s0.z], fd0 = feats[s0.w];
        float4 va0 = g_vtab[r0.x * N_NODES + d0.x];
        float4 vb0 = g_vtab[r0.y * N_NODES + d0.y];
        float4 vc0 = g_vtab[r0.z * N_NODES + d0.z];
        float4 vd0 = g_vtab[r0.w * N_NODES + d0.w];
        // Indices for group 1
        int j = i + stride;
        bool have1 = j < nvec;
        int4 s1, d1, r1;
        if (have1) { s1 = s4p[j]; d1 = d4p[j]; r1 = r4p[j]; }

        while (true) {
            // Issue group-1 gathers (independent of group-0 consume)
            float2 fa1, fb1, fc1, fd1;
            float4 va1, vb1, vc1, vd1;
            if (have1) {
                fa1 = feats[s1.x]; fb1 = feats[s1.y];
                fc1 = feats[s1.z]; fd1 = feats[s1.w];
                va1 = g_vtab[r1.x * N_NODES + d1.x];
                vb1 = g_vtab[r1.y * N_NODES + d1.y];
                vc1 = g_vtab[r1.z * N_NODES + d1.z];
                vd1 = g_vtab[r1.w * N_NODES + d1.w];
            }
            // Prefetch group-2 indices
            int k = j + stride;
            bool have2 = have1 && (k < nvec);
            int4 s2, d2, r2;
            if (have2) { s2 = s4p[k]; d2 = d4p[k]; r2 = r4p[k]; }

            // Consume group 0 (its gathers were issued one iteration ago)
            facc += fmaf(fa0.x, va0.x, fmaf(fa0.y, va0.y, va0.z))
                  + fmaf(fb0.x, vb0.x, fmaf(fb0.y, vb0.y, vb0.z))
                  + fmaf(fc0.x, vc0.x, fmaf(fc0.y, vc0.y, vc0.z))
                  + fmaf(fd0.x, vd0.x, fmaf(fd0.y, vd0.y, vd0.z));
            if (!have1) break;

            // Rotate pipeline
            fa0 = fa1; fb0 = fb1; fc0 = fc1; fd0 = fd1;
            va0 = va1; vb0 = vb1; vc0 = vc1; vd0 = vd1;
            s1 = s2; d1 = d2; r1 = r2;
            j = k; have1 = have2;
        }
        contrib = (double)facc;
    }
    // tail edges (if E not multiple of 4)
    for (int e = (nvec << 2) + blockIdx.x * TPB_E + threadIdx.x; e < E; e += stride) {
        float2 f = feats[src[e]];
        float4 v = g_vtab[et[e] * N_NODES + dst[e]];
        contrib += (double)fmaf(f.x, v.x, fmaf(f.y, v.y, v.z));
    }

    double bs = block_reduce(contrib, TPB_E);
    if (threadIdx.x == 0) {
        atomicAdd(&g_acc, bs);
        __threadfence();
        unsigned d = atomicAdd(&g_done, 1u);
        if (d == GRID_E - 1) {
            double logit = atomicAdd(&g_acc, 0.0) + (double)fc_b[0];
            out[0] = (float)(1.0 / (1.0 + exp(-logit)));
            g_acc = 0.0;       // reset for next graph replay
            g_done = 0u;
            g_ready = 0u;
        }
    }
}

extern "C" void kernel_launch(void* const* d_in, const int* in_sizes, int n_in,
                              void* d_out, int out_size) {
    const float* features = (const float*)d_in[0];
    const int*   src      = (const int*)d_in[1];
    const int*   dst      = (const int*)d_in[2];
    const int*   etype    = (const int*)d_in[3];
    const float* W_in     = (const float*)d_in[4];
    const float* b_in     = (const float*)d_in[5];
    const float* w_comp   = (const float*)d_in[6];
    const float* bases    = (const float*)d_in[7];
    const float* loop_w   = (const float*)d_in[8];
    const float* h_bias   = (const float*)d_in[9];
    const float* fc_W     = (const float*)d_in[10];
    const float* fc_b     = (const float*)d_in[11];
    int E = in_sizes[1];

    k_node<<<GRID_N, TPB_N>>>((const float2*)features,
                              W_in, b_in, w_comp, bases,
                              loop_w, h_bias, fc_W);
    k_edge<<<GRID_E, TPB_E>>>((const float2*)features, src, dst, etype,
                              fc_b, E, (float*)d_out);
}